// round 8
// baseline (speedup 1.0000x reference)
#include <cuda_runtime.h>
#include <cuda_fp16.h>
#include <cstdint>

#define E_EXPERTS 8
#define T_TOKENS  4096
#define D_MODEL   1024
#define F_FF      4096
#define TOPK      2
#define GROUPSZ   128

// ---------------- scratch ----------------
__device__ int    g_cnt[E_EXPERTS];
__device__ int    g_off[E_EXPERTS + 1];
__device__ int    g_tok[T_TOKENS * TOPK];
__device__ int    g_tok_eid[T_TOKENS * TOPK];
__device__ int    g_tok_slot[T_TOKENS * TOPK];
__device__ float  g_tok_coef[T_TOKENS * TOPK];
__device__ __half g_xh[(size_t)T_TOKENS * D_MODEL];
__device__ __half g_acth[(size_t)T_TOKENS * TOPK * F_FF];
__device__ float  g_y[(size_t)T_TOKENS * TOPK * D_MODEL];
// packed int4, layout [e][kb][w][n]; within a word the 8 codes for k=kb*32+w*8+j
// are stored at nibble slot (j&1)*4 + (j>>1) so that extraction i pairs (2i,2i+1).
__device__ uint32_t g_pw1[(size_t)E_EXPERTS * 32 * 4 * (2 * F_FF)];
__device__ uint32_t g_pw2[(size_t)E_EXPERTS * 128 * 4 * D_MODEL];

// ---------------- helpers ----------------
#define MMA_F16(c, a, b)                                                       \
    asm volatile(                                                              \
        "mma.sync.aligned.m16n8k16.row.col.f32.f16.f16.f32 "                   \
        "{%0,%1,%2,%3}, {%4,%5,%6,%7}, {%8,%9}, {%0,%1,%2,%3};\n"              \
        : "+f"((c)[0]), "+f"((c)[1]), "+f"((c)[2]), "+f"((c)[3])               \
        : "r"((a)[0]), "r"((a)[1]), "r"((a)[2]), "r"((a)[3]),                  \
          "r"((b)[0]), "r"((b)[1]))

__device__ __forceinline__ uint32_t h2u(__half2 h) {
    return *reinterpret_cast<uint32_t*>(&h);
}
// dequant one packed word -> 4 half2 words (8 consecutive k), exact integer path
__device__ __forceinline__ uint4 dq_word(uint32_t v, __half2 s2) {
    const uint32_t k1032 = 0x64086408u;           // half2(1032, 1032)
    uint4 r;
    uint32_t t0 = (v & 0x000F000Fu) | 0x64006400u;
    uint32_t t1 = ((v >> 4) & 0x000F000Fu) | 0x64006400u;
    uint32_t t2 = ((v >> 8) & 0x000F000Fu) | 0x64006400u;
    uint32_t t3 = ((v >> 12) & 0x000F000Fu) | 0x64006400u;
    r.x = h2u(__hmul2(__hsub2(*(__half2*)&t0, *(const __half2*)&k1032), s2));
    r.y = h2u(__hmul2(__hsub2(*(__half2*)&t1, *(const __half2*)&k1032), s2));
    r.z = h2u(__hmul2(__hsub2(*(__half2*)&t2, *(const __half2*)&k1032), s2));
    r.w = h2u(__hmul2(__hsub2(*(__half2*)&t3, *(const __half2*)&k1032), s2));
    return r;
}

// ---------------- routing (merged, single block) ----------------
__global__ void k_route_all(const float* __restrict__ gating) {
    __shared__ int s_cnt[E_EXPERTS];
    int tid = threadIdx.x;
    if (tid < E_EXPERTS) s_cnt[tid] = 0;
    __syncthreads();
    for (int t = tid; t < T_TOKENS; t += 1024) {
        float l[E_EXPERTS];
#pragma unroll
        for (int i = 0; i < E_EXPERTS; i++) l[i] = gating[t * E_EXPERTS + i];
        int ia = -1, ib = -1;
        float va = -1e30f, vb = -1e30f;
#pragma unroll
        for (int i = 0; i < E_EXPERTS; i++) {
            float v = l[i];
            if (v > va) { vb = va; ib = ia; va = v; ia = i; }
            else if (v > vb) { vb = v; ib = i; }
        }
        float eb = expf(vb - va);
        float inv = 1.0f / (1.0f + eb);
        g_tok_eid[2 * t + 0] = ia;
        g_tok_eid[2 * t + 1] = ib;
        g_tok_coef[2 * t + 0] = inv;
        g_tok_coef[2 * t + 1] = eb * inv;
        atomicAdd(&s_cnt[ia], 1);
        atomicAdd(&s_cnt[ib], 1);
    }
    __syncthreads();
    if (tid < E_EXPERTS) g_cnt[tid] = s_cnt[tid];
    // placement: warp e handles expert e, token order ascending
    int lane = tid & 31, e = tid >> 5;
    if (e < E_EXPERTS) {
        int off = 0;
        for (int i = 0; i < e; i++) off += s_cnt[i];
        if (lane == 0) {
            g_off[e] = off;
            if (e == E_EXPERTS - 1) g_off[E_EXPERTS] = off + s_cnt[e];
        }
        int cursor = off;
        for (int base = 0; base < T_TOKENS; base += 32) {
            int t = base + lane;
            int e0 = g_tok_eid[2 * t], e1 = g_tok_eid[2 * t + 1];
            bool m0 = (e0 == e), m1 = (e1 == e);
            bool m = m0 || m1;
            unsigned mask = __ballot_sync(0xffffffffu, m);
            if (m) {
                int pos = cursor + __popc(mask & ((1u << lane) - 1u));
                g_tok[pos] = t;
                g_tok_slot[2 * t + (m0 ? 0 : 1)] = pos;
            }
            cursor += __popc(mask);
        }
    }
}

// ---------------- prep ----------------
__global__ void k_xh(const float* __restrict__ x) {
    size_t i = ((size_t)blockIdx.x * 256 + threadIdx.x) * 4;
    float4 v = *(const float4*)(x + i);
    uint2 o;
    o.x = h2u(__floats2half2_rn(v.x, v.y));
    o.y = h2u(__floats2half2_rn(v.z, v.w));
    *(uint2*)(&g_xh[i]) = o;
}

__global__ void k_pack1(const int* __restrict__ w1q) {
    uint32_t idx = blockIdx.x * 256 + threadIdx.x;   // e[3]|kb[5]|w[2]|n[13]
    uint32_t n = idx & 8191, w = (idx >> 13) & 3, kb = (idx >> 15) & 31, e = idx >> 20;
    const int* src = w1q + ((size_t)e * D_MODEL + kb * 32 + w * 8) * (2 * F_FF) + n;
    uint32_t acc = 0;
#pragma unroll
    for (int j = 0; j < 8; j++)
        acc |= ((uint32_t)src[(size_t)j * (2 * F_FF)] & 15u) << (4 * ((j & 1) * 4 + (j >> 1)));
    g_pw1[idx] = acc;
}
__global__ void k_pack2(const int* __restrict__ w2q) {
    uint32_t idx = blockIdx.x * 256 + threadIdx.x;   // e[3]|kb[7]|w[2]|n[10]
    uint32_t n = idx & 1023, w = (idx >> 10) & 3, kb = (idx >> 12) & 127, e = idx >> 19;
    const int* src = w2q + ((size_t)e * F_FF + kb * 32 + w * 8) * D_MODEL + n;
    uint32_t acc = 0;
#pragma unroll
    for (int j = 0; j < 8; j++)
        acc |= ((uint32_t)src[(size_t)j * D_MODEL] & 15u) << (4 * ((j & 1) * 4 + (j >> 1)));
    g_pw2[idx] = acc;
}

// ---------------- GEMM1: act = silu(x@Wg)*(x@Wu), fp16 mma, double-buffered ----------------
// Block 128m x (64g + 64u), BK=32, 2 smem stages, 1 sync/tile.
__global__ __launch_bounds__(256, 2) void k_gemm1(const float* __restrict__ w1s)
{
    int e = blockIdx.z;
    int cnt = g_cnt[e];
    int row0 = blockIdx.y * 128;
    if (row0 >= cnt) return;
    int rows = min(cnt - row0, 128);
    int base = g_off[e];
    int n0 = blockIdx.x * 64;

    __shared__ __half As[2][128][40];
    __shared__ __half Bg[2][64][40];
    __shared__ __half Bu[2][64][40];
    __shared__ int toks[128];

    int tid = threadIdx.x;
    if (tid < 128) toks[tid] = g_tok[base + row0 + min(tid, rows - 1)];
    __syncthreads();

    int lane = tid & 31, wid = tid >> 5;
    int wm = wid >> 2, wn = wid & 3;
    int gid = lane >> 2, tig = lane & 3;

    float accG[4][2][4], accU[4][2][4];
#pragma unroll
    for (int i = 0; i < 4; i++)
#pragma unroll
        for (int j = 0; j < 2; j++)
#pragma unroll
            for (int r = 0; r < 4; r++) { accG[i][j][r] = 0.f; accU[i][j][r] = 0.f; }

    // fill mapping
    int ar = tid >> 1, ah = tid & 1;                       // A: row, 16-half chunk
    int bst = tid >> 7, brr = (tid >> 1) & 63, bw2 = (tid & 1) * 2;  // B: strip, n-row, word pair
    size_t bcol = (size_t)bst * F_FF + n0 + brr;
    const __half* xrow = g_xh + (size_t)toks[ar] * D_MODEL + ah * 16;
    const uint32_t* pwb = g_pw1 + (size_t)e * 32 * 4 * 8192 + bcol;
    const float* sbase = w1s + (size_t)e * 8 * (2 * F_FF) + bcol;

    uint4 aR[2][2];
    uint32_t bR[2][2];
#define LDG1(rs, kt)                                                           \
    do {                                                                       \
        const __half* xp = xrow + (kt) * 32;                                   \
        aR[rs][0] = *(const uint4*)(xp);                                       \
        aR[rs][1] = *(const uint4*)(xp + 8);                                   \
        const uint32_t* pw = pwb + ((size_t)(kt) * 4 + bw2) * 8192;            \
        bR[rs][0] = pw[0];                                                     \
        bR[rs][1] = pw[8192];                                                  \
    } while (0)
#define STS1(s, rs, kt)                                                        \
    do {                                                                       \
        *(uint4*)(&As[s][ar][ah * 16]) = aR[rs][0];                            \
        *(uint4*)(&As[s][ar][ah * 16 + 8]) = aR[rs][1];                        \
        __half2 s2 = __float2half2_rn(sbase[(size_t)((kt) >> 2) * (2 * F_FF)]);\
        __half(*B)[40] = bst ? Bu[s] : Bg[s];                                  \
        *(uint4*)(&B[brr][bw2 * 8]) = dq_word(bR[rs][0], s2);                  \
        *(uint4*)(&B[brr][bw2 * 8 + 8]) = dq_word(bR[rs][1], s2);              \
    } while (0)

    LDG1(0, 0);
    LDG1(1, 1);
    STS1(0, 0, 0);
    __syncthreads();

    const int NT = D_MODEL / 32;
    for (int kt = 0; kt < NT; kt++) {
        int s = kt & 1;
        if (kt + 2 < NT) LDG1(s, kt + 2);
        // mma: 2 k16 steps
#pragma unroll
        for (int ks = 0; ks < 2; ks++) {
            int kb2 = ks * 16 + 2 * tig;
            uint32_t bg[2][2], bu[2][2];
#pragma unroll
            for (int nf = 0; nf < 2; nf++) {
                int n = wn * 16 + nf * 8 + gid;
                bg[nf][0] = *(const uint32_t*)(&Bg[s][n][kb2]);
                bg[nf][1] = *(const uint32_t*)(&Bg[s][n][kb2 + 8]);
                bu[nf][0] = *(const uint32_t*)(&Bu[s][n][kb2]);
                bu[nf][1] = *(const uint32_t*)(&Bu[s][n][kb2 + 8]);
            }
#pragma unroll
            for (int mf = 0; mf < 4; mf++) {
                int m = wm * 64 + mf * 16;
                uint32_t a[4];
                a[0] = *(const uint32_t*)(&As[s][m + gid][kb2]);
                a[1] = *(const uint32_t*)(&As[s][m + gid + 8][kb2]);
                a[2] = *(const uint32_t*)(&As[s][m + gid][kb2 + 8]);
                a[3] = *(const uint32_t*)(&As[s][m + gid + 8][kb2 + 8]);
#pragma unroll
                for (int nf = 0; nf < 2; nf++) {
                    MMA_F16(accG[mf][nf], a, bg[nf]);
                    MMA_F16(accU[mf][nf], a, bu[nf]);
                }
            }
        }
        if (kt + 1 < NT) STS1(s ^ 1, (kt + 1) & 1, kt + 1);
        __syncthreads();
    }
#undef LDG1
#undef STS1

    // epilogue: silu(gate)*up -> fp16 act
#pragma unroll
    for (int mf = 0; mf < 4; mf++) {
#pragma unroll
        for (int half_i = 0; half_i < 2; half_i++) {
            int ml = wm * 64 + mf * 16 + gid + half_i * 8;
            if (ml < rows) {
                __half* dst = g_acth + (size_t)(base + row0 + ml) * F_FF;
#pragma unroll
                for (int nf = 0; nf < 2; nf++) {
                    int j = n0 + wn * 16 + nf * 8 + tig * 2;
                    float gv0 = accG[mf][nf][half_i * 2 + 0];
                    float gv1 = accG[mf][nf][half_i * 2 + 1];
                    float uv0 = accU[mf][nf][half_i * 2 + 0];
                    float uv1 = accU[mf][nf][half_i * 2 + 1];
                    float v0 = gv0 / (1.0f + __expf(-gv0)) * uv0;
                    float v1 = gv1 / (1.0f + __expf(-gv1)) * uv1;
                    *(uint32_t*)(dst + j) = h2u(__floats2half2_rn(v0, v1));
                }
            }
        }
    }
}

// ---------------- GEMM2: y = act @ dequant(w2), fp16 mma, double-buffered ----------------
// Block 128m x 128n, BK=32, 2 smem stages, 1 sync/tile.
__global__ __launch_bounds__(256, 2) void k_gemm2(const float* __restrict__ w2s)
{
    int e = blockIdx.z;
    int cnt = g_cnt[e];
    int row0 = blockIdx.y * 128;
    if (row0 >= cnt) return;
    int rows = min(cnt - row0, 128);
    int base = g_off[e];
    int n0 = blockIdx.x * 128;

    __shared__ __half As[2][128][40];
    __shared__ __half Bs[2][128][40];

    int tid = threadIdx.x;
    int lane = tid & 31, wid = tid >> 5;
    int wm = wid >> 2, wn = wid & 3;
    int gid = lane >> 2, tig = lane & 3;

    float acc[4][4][4];
#pragma unroll
    for (int i = 0; i < 4; i++)
#pragma unroll
        for (int j = 0; j < 4; j++)
#pragma unroll
            for (int r = 0; r < 4; r++) acc[i][j][r] = 0.f;

    int ar = tid >> 1, ah = tid & 1;
    int arv = min(ar, rows - 1);
    int brr = tid >> 1, bw2 = (tid & 1) * 2;
    const __half* arow = g_acth + (size_t)(base + row0 + arv) * F_FF + ah * 16;
    const uint32_t* pwb = g_pw2 + (size_t)e * 128 * 4 * 1024 + n0 + brr;
    const float* sbase = w2s + (size_t)e * 32 * D_MODEL + n0 + brr;

    uint4 aR[2][2];
    uint32_t bR[2][2];
#define LDG2(rs, kt)                                                           \
    do {                                                                       \
        const __half* ap = arow + (kt) * 32;                                   \
        aR[rs][0] = *(const uint4*)(ap);                                       \
        aR[rs][1] = *(const uint4*)(ap + 8);                                   \
        const uint32_t* pw = pwb + ((size_t)(kt) * 4 + bw2) * 1024;            \
        bR[rs][0] = pw[0];                                                     \
        bR[rs][1] = pw[1024];                                                  \
    } while (0)
#define STS2(s, rs, kt)                                                        \
    do {                                                                       \
        *(uint4*)(&As[s][ar][ah * 16]) = aR[rs][0];                            \
        *(uint4*)(&As[s][ar][ah * 16 + 8]) = aR[rs][1];                        \
        __half2 s2 = __float2half2_rn(sbase[(size_t)((kt) >> 2) * D_MODEL]);   \
        *(uint4*)(&Bs[s][brr][bw2 * 8]) = dq_word(bR[rs][0], s2);              \
        *(uint4*)(&Bs[s][brr][bw2 * 8 + 8]) = dq_word(bR[rs][1], s2);          \
    } while (0)

    LDG2(0, 0);
    LDG2(1, 1);
    STS2(0, 0, 0);
    __syncthreads();

    const int NT = F_FF / 32;
    for (int kt = 0; kt < NT; kt++) {
        int s = kt & 1;
        if (kt + 2 < NT) LDG2(s, kt + 2);
#pragma unroll
        for (int ks = 0; ks < 2; ks++) {
            int kb2 = ks * 16 + 2 * tig;
            uint32_t b[4][2];
#pragma unroll
            for (int nf = 0; nf < 4; nf++) {
                int n = wn * 32 + nf * 8 + gid;
                b[nf][0] = *(const uint32_t*)(&Bs[s][n][kb2]);
                b[nf][1] = *(const uint32_t*)(&Bs[s][n][kb2 + 8]);
            }
#pragma unroll
            for (int mf = 0; mf < 4; mf++) {
                int m = wm * 64 + mf * 16;
                uint32_t a[4];
                a[0] = *(const uint32_t*)(&As[s][m + gid][kb2]);
                a[1] = *(const uint32_t*)(&As[s][m + gid + 8][kb2]);
                a[2] = *(const uint32_t*)(&As[s][m + gid][kb2 + 8]);
                a[3] = *(const uint32_t*)(&As[s][m + gid + 8][kb2 + 8]);
#pragma unroll
                for (int nf = 0; nf < 4; nf++)
                    MMA_F16(acc[mf][nf], a, b[nf]);
            }
        }
        if (kt + 1 < NT) STS2(s ^ 1, (kt + 1) & 1, kt + 1);
        __syncthreads();
    }
#undef LDG2
#undef STS2

#pragma unroll
    for (int mf = 0; mf < 4; mf++) {
#pragma unroll
        for (int half_i = 0; half_i < 2; half_i++) {
            int ml = wm * 64 + mf * 16 + gid + half_i * 8;
            if (ml < rows) {
                float* dst = g_y + (size_t)(base + row0 + ml) * D_MODEL;
#pragma unroll
                for (int nf = 0; nf < 4; nf++) {
                    int j = n0 + wn * 32 + nf * 8 + tig * 2;
                    *(float2*)(dst + j) =
                        make_float2(acc[mf][nf][half_i * 2 + 0],
                                    acc[mf][nf][half_i * 2 + 1]);
                }
            }
        }
    }
}

// ---------------- combine ----------------
__global__ void k_combine(float* __restrict__ out) {
    int t = blockIdx.x;
    int d = threadIdx.x * 4;
    int s0 = g_tok_slot[2 * t], s1 = g_tok_slot[2 * t + 1];
    float c0 = g_tok_coef[2 * t], c1 = g_tok_coef[2 * t + 1];
    float4 y0 = *(const float4*)(&g_y[(size_t)s0 * D_MODEL + d]);
    float4 y1 = *(const float4*)(&g_y[(size_t)s1 * D_MODEL + d]);
    float4 o;
    o.x = c0 * y0.x + c1 * y1.x;
    o.y = c0 * y0.y + c1 * y1.y;
    o.z = c0 * y0.z + c1 * y1.z;
    o.w = c0 * y0.w + c1 * y1.w;
    *(float4*)(out + (size_t)t * D_MODEL + d) = o;
}

// ---------------- launch ----------------
extern "C" void kernel_launch(void* const* d_in, const int* in_sizes, int n_in,
                              void* d_out, int out_size) {
    const float* x      = (const float*)d_in[0];
    const float* gating = (const float*)d_in[1];
    const int*   w1q    = (const int*)d_in[2];
    const int*   w2q    = (const int*)d_in[3];
    const float* w1s    = (const float*)d_in[4];
    const float* w2s    = (const float*)d_in[5];
    float* out = (float*)d_out;
    (void)in_sizes; (void)n_in; (void)out_size;

    k_xh<<<(T_TOKENS * D_MODEL) / (256 * 4), 256>>>(x);
    k_pack1<<<(8u * 32 * 4 * 8192) / 256, 256>>>(w1q);
    k_pack2<<<(8u * 128 * 4 * 1024) / 256, 256>>>(w2q);
    k_route_all<<<1, 1024>>>(gating);

    dim3 g1(F_FF / 64, T_TOKENS / 128, E_EXPERTS);     // 64 x 32 x 8
    k_gemm1<<<g1, 256>>>(w1s);

    dim3 g2(D_MODEL / 128, T_TOKENS / 128, E_EXPERTS); // 8 x 32 x 8
    k_gemm2<<<g2, 256>>>(w2s);

    k_combine<<<T_TOKENS, 256>>>(out);
}